// round 9
// baseline (speedup 1.0000x reference)
#include <cuda_runtime.h>
#include <cuda_fp16.h>
#include <stdint.h>

// Problem constants: B=8, CK=64, H=W=64 -> HW=4096
#define BATCH 8
#define CKDIM 64
#define HW    4096
#define NGROUPS 256           // (b, n_tile) groups: 8 * 32
#define GROUP_CTAS 32         // m-tiles per group
#define NTILEPAIRS 4096       // tickets; tile ids T and T+4096

// SMEM: two A/B fp16 tile buffers + two reduce bufs + ticket
#define BUF0 0
#define BUF1 32768
#define BOFF 16384            // B tile offset within a buffer
#define RED1 65536
#define RED2 (65536 + 512)
#define TKT  (65536 + 1024)
#define SMEM_BYTES (65536 + 1024 + 16)

__device__ float g_sums[BATCH * HW];
__device__ unsigned g_cnt[NGROUPS];
__device__ unsigned g_ticket;

__global__ void init_kernel() {
    int i = blockIdx.x * blockDim.x + threadIdx.x;
    if (i < BATCH * HW) g_sums[i] = 0.0f;
    if (i < NGROUPS) g_cnt[i] = 0u;
    if (i == 0) g_ticket = 0u;
}

__device__ __forceinline__ uint32_t smem_u32(const void* p) {
    uint32_t a;
    asm("{ .reg .u64 t; cvta.to.shared.u64 t, %1; cvt.u32.u64 %0, t; }"
        : "=r"(a) : "l"(p));
    return a;
}
__device__ __forceinline__ uint32_t swz(uint32_t off) {
    return off ^ ((off >> 3) & 0x70);
}
__device__ __forceinline__ uint32_t pack2h(float v0, float v1) {
    __half2 h = __floats2half2_rn(v0, v1);
    return *(uint32_t*)&h;
}
__device__ __forceinline__ void sts128(uint32_t addr, uint32_t r0, uint32_t r1,
                                       uint32_t r2, uint32_t r3) {
    asm volatile("st.shared.v4.b32 [%0], {%1,%2,%3,%4};"
                 :: "r"(addr), "r"(r0), "r"(r1), "r"(r2), "r"(r3));
}
__device__ __forceinline__ void ldsm4(uint32_t addr, uint32_t* r) {
    asm volatile("ldmatrix.sync.aligned.m8n8.x4.shared.b16 {%0,%1,%2,%3}, [%4];"
                 : "=r"(r[0]), "=r"(r[1]), "=r"(r[2]), "=r"(r[3]) : "r"(addr));
}
__device__ __forceinline__ void mma16816(float* d, const uint32_t* a, const uint32_t* b) {
    asm volatile(
        "mma.sync.aligned.m16n8k16.row.col.f32.f16.f16.f32 "
        "{%0,%1,%2,%3}, {%4,%5,%6,%7}, {%8,%9}, {%0,%1,%2,%3};"
        : "+f"(d[0]), "+f"(d[1]), "+f"(d[2]), "+f"(d[3])
        : "r"(a[0]), "r"(a[1]), "r"(a[2]), "r"(a[3]), "r"(b[0]), "r"(b[1]));
}

// Load one 128x128 tile pair (A=Mk rows, B=Qk/8) into SMEM buffer.
// 1024 threads: slot=(tid) -> kb=(tid>>5)&7, r=(tid>>8)*32+lane.
// STS.128 conflict-free: swizzle unit = kb ^ (r&7), distinct across lanes 0..7.
__device__ __forceinline__ void load_tile(uint32_t dst, const float* __restrict__ Ap,
                                          const float* __restrict__ Bp, int tid) {
    const int lane = tid & 31;
    const int kb = (tid >> 5) & 7;
    const int r  = (tid >> 8) * 32 + lane;
    const int c0 = kb * 8;
    float a[8], bv[8];
#pragma unroll
    for (int j = 0; j < 8; j++) a[j]  = Ap[(size_t)(c0 + j) * HW + r];
#pragma unroll
    for (int j = 0; j < 8; j++) bv[j] = Bp[(size_t)(c0 + j) * HW + r] * 0.125f;
    uint32_t aw[4], bw[4];
#pragma unroll
    for (int j = 0; j < 4; j++) {
        aw[j] = pack2h(a[2 * j],  a[2 * j + 1]);
        bw[j] = pack2h(bv[2 * j], bv[2 * j + 1]);
    }
    const uint32_t sa = swz((uint32_t)(r * 128 + kb * 16));
    sts128(dst + sa, aw[0], aw[1], aw[2], aw[3]);
    sts128(dst + BOFF + sa, bw[0], bw[1], bw[2], bw[3]);
}

// MMA for one tile: 4x8 warp grid, warp tile 32(m) x 16(n), acc[2][2][4].
__device__ __forceinline__ void mma_tile(uint32_t src, float acc[2][2][4],
                                         int wm, int wn, int lane) {
    const int a_row = wm * 32 + (lane & 7) + ((lane >> 3) & 1) * 8;
    const int a_kb  = (lane >> 4) * 16;
    const int b_row = wn * 16 + (lane & 7) + (lane >> 4) * 8;
    const int b_kb  = ((lane >> 3) & 1) * 16;
#pragma unroll
    for (int ks = 0; ks < 4; ks++) {
        const int kbase = ks * 32;
        uint32_t ah[2][4], bf[4];
        ldsm4(src + swz((uint32_t)(a_row * 128 + kbase + a_kb)), ah[0]);
        ldsm4(src + swz((uint32_t)((a_row + 16) * 128 + kbase + a_kb)), ah[1]);
        ldsm4(src + BOFF + swz((uint32_t)(b_row * 128 + kbase + b_kb)), bf);
#pragma unroll
        for (int mi = 0; mi < 2; mi++)
#pragma unroll
            for (int ni = 0; ni < 2; ni++)
                mma16816(acc[mi][ni], ah[mi], &bf[ni * 2]);
    }
}

// exp in place + column partial sums into SMEM red buffer.
__device__ __forceinline__ void exp_sums(float acc[2][2][4], float* red,
                                         int lane, int wn) {
    float cs[4] = {0.f, 0.f, 0.f, 0.f};
#pragma unroll
    for (int mi = 0; mi < 2; mi++)
#pragma unroll
        for (int ni = 0; ni < 2; ni++) {
            acc[mi][ni][0] = __expf(acc[mi][ni][0]);
            acc[mi][ni][1] = __expf(acc[mi][ni][1]);
            acc[mi][ni][2] = __expf(acc[mi][ni][2]);
            acc[mi][ni][3] = __expf(acc[mi][ni][3]);
            cs[2 * ni]     += acc[mi][ni][0] + acc[mi][ni][2];
            cs[2 * ni + 1] += acc[mi][ni][1] + acc[mi][ni][3];
        }
#pragma unroll
    for (int msk = 4; msk < 32; msk <<= 1)
#pragma unroll
        for (int q = 0; q < 4; q++)
            cs[q] += __shfl_xor_sync(0xFFFFFFFFu, cs[q], msk);
    if (lane < 4) {
#pragma unroll
        for (int ni = 0; ni < 2; ni++) {
            atomicAdd(&red[wn * 16 + ni * 8 + 2 * lane],     cs[2 * ni]);
            atomicAdd(&red[wn * 16 + ni * 8 + 2 * lane + 1], cs[2 * ni + 1]);
        }
    }
}

__device__ __forceinline__ void signal_grp(unsigned* cnt) {
    asm volatile("red.release.gpu.global.add.u32 [%0], %1;"
                 :: "l"(cnt), "r"(1u) : "memory");
}
__device__ __forceinline__ void wait_grp(unsigned* cnt) {
    unsigned v;
    do {
        asm volatile("ld.acquire.gpu.global.u32 %0, [%1];"
                     : "=r"(v) : "l"(cnt) : "memory");
        if (v < GROUP_CTAS) __nanosleep(64);
    } while (v < GROUP_CTAS);
}

// normalize from L2-coherent sums, single store of final softmax.
__device__ __forceinline__ void store_tile(const float acc[2][2][4],
                                           const float* gs, float* __restrict__ outb,
                                           int wm, int wn, int lane) {
    const int mrow = wm * 32 + (lane >> 2);
    const int ncl  = wn * 16 + 2 * (lane & 3);
    float rs[4];
#pragma unroll
    for (int ni = 0; ni < 2; ni++) {
        rs[2 * ni]     = __fdividef(1.0f, __ldcg(&gs[ncl + ni * 8]));
        rs[2 * ni + 1] = __fdividef(1.0f, __ldcg(&gs[ncl + ni * 8 + 1]));
    }
#pragma unroll
    for (int mi = 0; mi < 2; mi++)
#pragma unroll
        for (int ni = 0; ni < 2; ni++) {
            size_t ro = (size_t)(mrow + mi * 16) * HW + ncl + ni * 8;
            __stcs((float2*)(outb + ro),
                   make_float2(acc[mi][ni][0] * rs[2 * ni], acc[mi][ni][1] * rs[2 * ni + 1]));
            __stcs((float2*)(outb + ro + (size_t)8 * HW),
                   make_float2(acc[mi][ni][2] * rs[2 * ni], acc[mi][ni][3] * rs[2 * ni + 1]));
        }
}

// Two-tile pipelined fused kernel: compute/signal both tiles, then wait/store.
// Tile1 = ticket T, tile2 = T + 4096 (different groups): by the time W1 is
// reached, grp1's 32 signals arrived a full tile-compute earlier -> spin ~0.
__global__ __launch_bounds__(1024, 1)
void gemm_softmax_fused(const float* __restrict__ Mk, const float* __restrict__ Qk,
                        float* __restrict__ out) {
    extern __shared__ char smem[];
    const uint32_t sb = smem_u32(smem);
    const int tid = threadIdx.x, lane = tid & 31, wid = tid >> 5;
    const int wm = wid >> 3, wn = wid & 7;           // 4x8 warp grid

    if (tid == 0)
        *(unsigned*)(smem + TKT) = atomicAdd(&g_ticket, 1u);
    if (tid < 256) ((float*)(smem + RED1))[tid] = 0.0f;   // zeroes RED1+RED2
    __syncthreads();
    const unsigned T = *(const unsigned*)(smem + TKT);

    // tile decomposition
    const unsigned id1 = T, id2 = T + NTILEPAIRS;
    const int m1 = (int)(id1 & 31u), g1 = (int)(id1 >> 5);
    const int n1 = g1 & 31, b1 = g1 >> 5;
    const int m2 = (int)(id2 & 31u), g2 = (int)(id2 >> 5);
    const int n2 = g2 & 31, b2 = g2 >> 5;

    const float* A1 = Mk + (size_t)b1 * CKDIM * HW + m1 * 128;
    const float* B1 = Qk + (size_t)b1 * CKDIM * HW + n1 * 128;
    const float* A2 = Mk + (size_t)b2 * CKDIM * HW + m2 * 128;
    const float* B2 = Qk + (size_t)b2 * CKDIM * HW + n2 * 128;
    float* gs1 = &g_sums[b1 * HW + n1 * 128];
    float* gs2 = &g_sums[b2 * HW + n2 * 128];

    float acc1[2][2][4], acc2[2][2][4];
#pragma unroll
    for (int i = 0; i < 2; i++)
#pragma unroll
        for (int j = 0; j < 2; j++)
#pragma unroll
            for (int q = 0; q < 4; q++) { acc1[i][j][q] = 0.f; acc2[i][j][q] = 0.f; }

    // ---- tile 1: load, MMA ----
    load_tile(sb + BUF0, A1, B1, tid);
    __syncthreads();
    mma_tile(sb + BUF0, acc1, wm, wn, lane);

    // ---- tile 2 load overlapped with tile 1 epilogue ----
    load_tile(sb + BUF1, A2, B2, tid);
    exp_sums(acc1, (float*)(smem + RED1), lane, wn);
    __syncthreads();                         // red1 + buf1 complete
    if (tid < 128) atomicAdd(&gs1[tid], ((float*)(smem + RED1))[tid]);
    __syncthreads();
    if (tid == 0) signal_grp(&g_cnt[g1]);

    // ---- tile 2: MMA, epilogue, signal ----
    mma_tile(sb + BUF1, acc2, wm, wn, lane);
    exp_sums(acc2, (float*)(smem + RED2), lane, wn);
    __syncthreads();
    if (tid < 128) atomicAdd(&gs2[tid], ((float*)(smem + RED2))[tid]);
    __syncthreads();
    if (tid == 0) signal_grp(&g_cnt[g2]);

    // ---- wait (should be near-zero) + store both tiles ----
    if (tid == 0) wait_grp(&g_cnt[g1]);
    __syncthreads();
    store_tile(acc1, gs1, out + (size_t)(b1 * HW + m1 * 128) * HW + n1 * 128,
               wm, wn, lane);

    if (tid == 0) wait_grp(&g_cnt[g2]);
    __syncthreads();
    store_tile(acc2, gs2, out + (size_t)(b2 * HW + m2 * 128) * HW + n2 * 128,
               wm, wn, lane);
}

extern "C" void kernel_launch(void* const* d_in, const int* in_sizes, int n_in,
                              void* d_out, int out_size) {
    const float* Mk = (const float*)d_in[0];
    const float* Qk = (const float*)d_in[1];
    float* out = (float*)d_out;

    cudaFuncSetAttribute(gemm_softmax_fused,
                         cudaFuncAttributeMaxDynamicSharedMemorySize, SMEM_BYTES);

    init_kernel<<<(BATCH * HW + 255) / 256, 256>>>();

    gemm_softmax_fused<<<NTILEPAIRS, 1024, SMEM_BYTES>>>(Mk, Qk, out);
}

// round 10
// speedup vs baseline: 1.2720x; 1.2720x over previous
#include <cuda_runtime.h>
#include <cuda_fp16.h>
#include <stdint.h>

// Problem constants: B=8, CK=64, H=W=64 -> HW=4096
#define BATCH 8
#define CKDIM 64
#define HW    4096
#define NGROUPS 256           // (b, n_tile) groups: 8 * 32
#define GROUP_CTAS 32         // m-tiles (tickets) per group
#define NTILES 8192

// SMEM layout
#define TILE_A 0              // Mk fp16 128x64 SW128: 16 KB
#define TILE_B 16384          // Qk/8 fp16: 16 KB
#define E_OFF  32768          // tile1 exp values fp32: 32 slots x 512 thr = 64 KB
#define RED1_OFF 98304        // 128 floats
#define RED2_OFF 98816
#define TKT_OFF  99328
#define SMEM_BYTES 99344

__device__ float g_sums[BATCH * HW];
__device__ unsigned g_cnt[NGROUPS];
__device__ unsigned g_ticket;

__global__ void init_kernel() {
    int i = blockIdx.x * blockDim.x + threadIdx.x;
    if (i < BATCH * HW) g_sums[i] = 0.0f;
    if (i < NGROUPS) g_cnt[i] = 0u;
    if (i == 0) g_ticket = 0u;
}

__device__ __forceinline__ uint32_t smem_u32(const void* p) {
    uint32_t a;
    asm("{ .reg .u64 t; cvta.to.shared.u64 t, %1; cvt.u32.u64 %0, t; }"
        : "=r"(a) : "l"(p));
    return a;
}
__device__ __forceinline__ uint32_t swz(uint32_t off) {
    return off ^ ((off >> 3) & 0x70);
}
__device__ __forceinline__ uint32_t pack2h(float v0, float v1) {
    __half2 h = __floats2half2_rn(v0, v1);
    return *(uint32_t*)&h;
}
__device__ __forceinline__ void sts128(uint32_t addr, uint32_t r0, uint32_t r1,
                                       uint32_t r2, uint32_t r3) {
    asm volatile("st.shared.v4.b32 [%0], {%1,%2,%3,%4};"
                 :: "r"(addr), "r"(r0), "r"(r1), "r"(r2), "r"(r3));
}
__device__ __forceinline__ void ldsm4(uint32_t addr, uint32_t* r) {
    asm volatile("ldmatrix.sync.aligned.m8n8.x4.shared.b16 {%0,%1,%2,%3}, [%4];"
                 : "=r"(r[0]), "=r"(r[1]), "=r"(r[2]), "=r"(r[3]) : "r"(addr));
}
__device__ __forceinline__ void mma16816(float* d, const uint32_t* a, const uint32_t* b) {
    asm volatile(
        "mma.sync.aligned.m16n8k16.row.col.f32.f16.f16.f32 "
        "{%0,%1,%2,%3}, {%4,%5,%6,%7}, {%8,%9}, {%0,%1,%2,%3};"
        : "+f"(d[0]), "+f"(d[1]), "+f"(d[2]), "+f"(d[3])
        : "r"(a[0]), "r"(a[1]), "r"(a[2]), "r"(a[3]), "r"(b[0]), "r"(b[1]));
}
__device__ __forceinline__ void signal_grp(unsigned* cnt) {
    asm volatile("red.release.gpu.global.add.u32 [%0], %1;"
                 :: "l"(cnt), "r"(1u) : "memory");
}
__device__ __forceinline__ void wait_grp(unsigned* cnt) {
    unsigned v;
    do {
        asm volatile("ld.acquire.gpu.global.u32 %0, [%1];"
                     : "=r"(v) : "l"(cnt) : "memory");
        if (v < GROUP_CTAS) __nanosleep(64);
    } while (v < GROUP_CTAS);
}

// Load one 128x64 fp16 tile into SMEM (conflict-free STS.128), 512 threads.
// scale: multiply values before pack (1.0 for A, 0.125 for B).
__device__ __forceinline__ void load_half(uint32_t dst, const float* __restrict__ P,
                                          float scale, int tid) {
    const int lane = tid & 31;
#pragma unroll
    for (int it = 0; it < 2; it++) {
        const int slot = (tid >> 5) * 2 + it;
        const int rg = slot >> 3, kb = slot & 7;
        const int r = rg * 32 + lane;
        const int c0 = kb * 8;
        float v[8];
#pragma unroll
        for (int j = 0; j < 8; j++) v[j] = P[(size_t)(c0 + j) * HW + r] * scale;
        uint32_t w[4];
#pragma unroll
        for (int j = 0; j < 4; j++) w[j] = pack2h(v[2 * j], v[2 * j + 1]);
        sts128(dst + swz((uint32_t)(r * 128 + kb * 16)), w[0], w[1], w[2], w[3]);
    }
}

// MMA for one tile, R8 layout: 4x4 warp grid, warp tile 32(m)x32(n).
__device__ __forceinline__ void mma_tile(uint32_t sb, float acc[2][4][4],
                                         int wm, int wn, int lane) {
    const int a_row = wm * 32 + (lane & 7) + ((lane >> 3) & 1) * 8;
    const int a_kb  = (lane >> 4) * 16;
    const int b_row = wn * 32 + (lane & 7) + (lane >> 4) * 8;
    const int b_kb  = ((lane >> 3) & 1) * 16;
#pragma unroll
    for (int ks = 0; ks < 4; ks++) {
        const int kbase = ks * 32;
        uint32_t ah[2][4], bf[8];
        ldsm4(sb + TILE_A + swz((uint32_t)(a_row * 128 + kbase + a_kb)), ah[0]);
        ldsm4(sb + TILE_A + swz((uint32_t)((a_row + 16) * 128 + kbase + a_kb)), ah[1]);
        ldsm4(sb + TILE_B + swz((uint32_t)(b_row * 128 + kbase + b_kb)), &bf[0]);
        ldsm4(sb + TILE_B + swz((uint32_t)((b_row + 16) * 128 + kbase + b_kb)), &bf[4]);
#pragma unroll
        for (int mi = 0; mi < 2; mi++)
#pragma unroll
            for (int ni = 0; ni < 4; ni++)
                mma16816(acc[mi][ni], ah[mi], &bf[ni * 2]);
    }
}

// exp in place + column partial sums into red; optionally park values in E buf.
__device__ __forceinline__ void exp_sums(uint32_t sb, float acc[2][4][4], float* red,
                                         int tid, int lane, int wn, bool write_e) {
    float cs[8];
#pragma unroll
    for (int q = 0; q < 8; q++) cs[q] = 0.0f;
    float* E = (float*)0;
    if (write_e) E = (float*)((char*)0 + 0);  // placeholder; real addr below via sb
#pragma unroll
    for (int mi = 0; mi < 2; mi++)
#pragma unroll
        for (int ni = 0; ni < 4; ni++) {
#pragma unroll
            for (int q = 0; q < 4; q++)
                acc[mi][ni][q] = __expf(acc[mi][ni][q]);
            cs[2 * ni]     += acc[mi][ni][0] + acc[mi][ni][2];
            cs[2 * ni + 1] += acc[mi][ni][1] + acc[mi][ni][3];
            if (write_e) {
                const int sbase = (mi * 4 + ni) * 4;
#pragma unroll
                for (int q = 0; q < 4; q++)
                    asm volatile("st.shared.b32 [%0], %1;"
                        :: "r"(sb + E_OFF + (uint32_t)(((sbase + q) * 512 + tid) * 4)),
                           "f"(acc[mi][ni][q]));
            }
        }
#pragma unroll
    for (int msk = 4; msk < 32; msk <<= 1)
#pragma unroll
        for (int q = 0; q < 8; q++)
            cs[q] += __shfl_xor_sync(0xFFFFFFFFu, cs[q], msk);
    if (lane < 4) {
#pragma unroll
        for (int ni = 0; ni < 4; ni++) {
            atomicAdd(&red[wn * 32 + ni * 8 + 2 * lane],     cs[2 * ni]);
            atomicAdd(&red[wn * 32 + ni * 8 + 2 * lane + 1], cs[2 * ni + 1]);
        }
    }
}

// Two consecutive tickets per CTA: same group in 15/16 cases (B reuse),
// deferred stores hide the group-wait behind tile2's compute.
__global__ __launch_bounds__(512, 2)
void gemm_softmax_fused(const float* __restrict__ Mk, const float* __restrict__ Qk,
                        float* __restrict__ out) {
    extern __shared__ char smem[];
    const uint32_t sb = smem_u32(smem);
    const int tid = threadIdx.x, lane = tid & 31, wid = tid >> 5;
    const int wm = wid >> 2, wn = wid & 3;

    if (tid == 0)
        *(unsigned*)(smem + TKT_OFF) = atomicAdd(&g_ticket, 2u);
    if (tid < 256) ((float*)(smem + RED1_OFF))[tid] = 0.0f;   // RED1+RED2
    __syncthreads();
    const unsigned t1 = *(const unsigned*)(smem + TKT_OFF);
    const unsigned t2 = t1 + 1;
    const int m1 = (int)(t1 & 31u), g1 = (int)(t1 >> 5);
    const int m2 = (int)(t2 & 31u), g2 = (int)(t2 >> 5);
    const int n1 = g1 & 31, b1 = g1 >> 5;
    const int n2 = g2 & 31, b2 = g2 >> 5;

    const float* A1 = Mk + (size_t)b1 * CKDIM * HW + m1 * 128;
    const float* B1 = Qk + (size_t)b1 * CKDIM * HW + n1 * 128;
    const float* A2 = Mk + (size_t)b2 * CKDIM * HW + m2 * 128;
    const float* B2 = Qk + (size_t)b2 * CKDIM * HW + n2 * 128;
    float* gs1 = &g_sums[b1 * HW + n1 * 128];
    float* gs2 = &g_sums[b2 * HW + n2 * 128];
    float* red1 = (float*)(smem + RED1_OFF);
    float* red2 = (float*)(smem + RED2_OFF);

    float acc[2][4][4];
#pragma unroll
    for (int i = 0; i < 2; i++)
#pragma unroll
        for (int j = 0; j < 4; j++)
#pragma unroll
            for (int q = 0; q < 4; q++) acc[i][j][q] = 0.0f;

    // ---- tile 1: load, MMA, exp -> E buffer, contribute, signal ----
    load_half(sb + TILE_A, A1, 1.0f, tid);
    load_half(sb + TILE_B, B1, 0.125f, tid);
    __syncthreads();
    mma_tile(sb, acc, wm, wn, lane);
    exp_sums(sb, acc, red1, tid, lane, wn, true);
    __syncthreads();                       // red1 + E done; tile reads done
    if (tid < 128) atomicAdd(&gs1[tid], red1[tid]);

    // ---- tile 2 loads (reuse B if same group), overlap with signal ----
    load_half(sb + TILE_A, A2, 1.0f, tid);
    if (g2 != g1) load_half(sb + TILE_B, B2, 0.125f, tid);
    __syncthreads();                       // gs1 contributions + loads visible
    if (tid == 0) signal_grp(&g_cnt[g1]);

    // ---- tile 2: MMA, exp (stays in regs), contribute, signal ----
#pragma unroll
    for (int i = 0; i < 2; i++)
#pragma unroll
        for (int j = 0; j < 4; j++)
#pragma unroll
            for (int q = 0; q < 4; q++) acc[i][j][q] = 0.0f;
    mma_tile(sb, acc, wm, wn, lane);
    exp_sums(sb, acc, red2, tid, lane, wn, false);
    __syncthreads();
    if (tid < 128) atomicAdd(&gs2[tid], red2[tid]);
    __syncthreads();
    if (tid == 0) signal_grp(&g_cnt[g2]);

    // ---- store tile 1 from E (group long since complete) ----
    const int mrow_l = wm * 32 + (lane >> 2);
    const int ncl    = wn * 32 + 2 * (lane & 3);
    if (tid == 0) wait_grp(&g_cnt[g1]);
    __syncthreads();
    {
        float rs[8];
#pragma unroll
        for (int ni = 0; ni < 4; ni++) {
            rs[2 * ni]     = __fdividef(1.0f, __ldcg(&gs1[ncl + ni * 8]));
            rs[2 * ni + 1] = __fdividef(1.0f, __ldcg(&gs1[ncl + ni * 8 + 1]));
        }
        float* outb = out + (size_t)(b1 * HW + m1 * 128) * HW + n1 * 128;
#pragma unroll
        for (int mi = 0; mi < 2; mi++)
#pragma unroll
            for (int ni = 0; ni < 4; ni++) {
                const int sbase = (mi * 4 + ni) * 4;
                float e[4];
#pragma unroll
                for (int q = 0; q < 4; q++)
                    asm volatile("ld.shared.b32 %0, [%1];" : "=f"(e[q])
                        : "r"(sb + E_OFF + (uint32_t)(((sbase + q) * 512 + tid) * 4)));
                size_t ro = (size_t)(mrow_l + mi * 16) * HW + ncl + ni * 8;
                __stcs((float2*)(outb + ro),
                       make_float2(e[0] * rs[2 * ni], e[1] * rs[2 * ni + 1]));
                __stcs((float2*)(outb + ro + (size_t)8 * HW),
                       make_float2(e[2] * rs[2 * ni], e[3] * rs[2 * ni + 1]));
            }
    }

    // ---- store tile 2 from registers ----
    if (tid == 0) wait_grp(&g_cnt[g2]);
    __syncthreads();
    {
        float rs[8];
#pragma unroll
        for (int ni = 0; ni < 4; ni++) {
            rs[2 * ni]     = __fdividef(1.0f, __ldcg(&gs2[ncl + ni * 8]));
            rs[2 * ni + 1] = __fdividef(1.0f, __ldcg(&gs2[ncl + ni * 8 + 1]));
        }
        float* outb = out + (size_t)(b2 * HW + m2 * 128) * HW + n2 * 128;
#pragma unroll
        for (int mi = 0; mi < 2; mi++)
#pragma unroll
            for (int ni = 0; ni < 4; ni++) {
                size_t ro = (size_t)(mrow_l + mi * 16) * HW + ncl + ni * 8;
                __stcs((float2*)(outb + ro),
                       make_float2(acc[mi][ni][0] * rs[2 * ni],
                                   acc[mi][ni][1] * rs[2 * ni + 1]));
                __stcs((float2*)(outb + ro + (size_t)8 * HW),
                       make_float2(acc[mi][ni][2] * rs[2 * ni],
                                   acc[mi][ni][3] * rs[2 * ni + 1]));
            }
    }
}

extern "C" void kernel_launch(void* const* d_in, const int* in_sizes, int n_in,
                              void* d_out, int out_size) {
    const float* Mk = (const float*)d_in[0];
    const float* Qk = (const float*)d_in[1];
    float* out = (float*)d_out;

    cudaFuncSetAttribute(gemm_softmax_fused,
                         cudaFuncAttributeMaxDynamicSharedMemorySize, SMEM_BYTES);

    init_kernel<<<(BATCH * HW + 255) / 256, 256>>>();

    gemm_softmax_fused<<<NTILES / 2, 512, SMEM_BYTES>>>(Mk, Qk, out);
}

// round 11
// speedup vs baseline: 1.3039x; 1.0251x over previous
#include <cuda_runtime.h>
#include <cuda_fp16.h>
#include <stdint.h>

// Problem constants: B=8, CK=64, H=W=64 -> HW=4096
#define BATCH 8
#define CKDIM 64
#define HW    4096
#define NGROUPS 256           // (b, n_tile) groups: 8 * 32
#define GROUP_CTAS 32         // m-tiles (tickets) per group
#define NTILES 8192

// SMEM layout
#define TILE_A 0              // Mk fp16 128x64 SW128: 16 KB
#define TILE_B 16384          // Qk/8 fp16: 16 KB
#define E_OFF  32768          // tile1 exp fp16x2: 4 segs x 512 thr x 16B = 32 KB
#define RED1_OFF 65536        // 128 floats
#define RED2_OFF 66048
#define TKT_OFF  66560
#define SMEM_BYTES 66576

__device__ float g_sums[BATCH * HW];
__device__ unsigned g_cnt[NGROUPS];
__device__ unsigned g_ticket;

__global__ void init_kernel() {
    int i = blockIdx.x * blockDim.x + threadIdx.x;
    if (i < BATCH * HW) g_sums[i] = 0.0f;
    if (i < NGROUPS) g_cnt[i] = 0u;
    if (i == 0) g_ticket = 0u;
}

__device__ __forceinline__ uint32_t smem_u32(const void* p) {
    uint32_t a;
    asm("{ .reg .u64 t; cvta.to.shared.u64 t, %1; cvt.u32.u64 %0, t; }"
        : "=r"(a) : "l"(p));
    return a;
}
__device__ __forceinline__ uint32_t swz(uint32_t off) {
    return off ^ ((off >> 3) & 0x70);
}
__device__ __forceinline__ uint32_t pack2h(float v0, float v1) {
    __half2 h = __floats2half2_rn(v0, v1);
    return *(uint32_t*)&h;
}
__device__ __forceinline__ void sts128(uint32_t addr, uint32_t r0, uint32_t r1,
                                       uint32_t r2, uint32_t r3) {
    asm volatile("st.shared.v4.b32 [%0], {%1,%2,%3,%4};"
                 :: "r"(addr), "r"(r0), "r"(r1), "r"(r2), "r"(r3));
}
__device__ __forceinline__ void lds128(uint32_t addr, uint32_t* r) {
    asm volatile("ld.shared.v4.b32 {%0,%1,%2,%3}, [%4];"
                 : "=r"(r[0]), "=r"(r[1]), "=r"(r[2]), "=r"(r[3]) : "r"(addr));
}
__device__ __forceinline__ void ldsm4(uint32_t addr, uint32_t* r) {
    asm volatile("ldmatrix.sync.aligned.m8n8.x4.shared.b16 {%0,%1,%2,%3}, [%4];"
                 : "=r"(r[0]), "=r"(r[1]), "=r"(r[2]), "=r"(r[3]) : "r"(addr));
}
__device__ __forceinline__ void mma16816(float* d, const uint32_t* a, const uint32_t* b) {
    asm volatile(
        "mma.sync.aligned.m16n8k16.row.col.f32.f16.f16.f32 "
        "{%0,%1,%2,%3}, {%4,%5,%6,%7}, {%8,%9}, {%0,%1,%2,%3};"
        : "+f"(d[0]), "+f"(d[1]), "+f"(d[2]), "+f"(d[3])
        : "r"(a[0]), "r"(a[1]), "r"(a[2]), "r"(a[3]), "r"(b[0]), "r"(b[1]));
}
__device__ __forceinline__ void signal_grp(unsigned* cnt) {
    asm volatile("red.release.gpu.global.add.u32 [%0], %1;"
                 :: "l"(cnt), "r"(1u) : "memory");
}
__device__ __forceinline__ void wait_grp(unsigned* cnt) {
    unsigned v;
    do {
        asm volatile("ld.acquire.gpu.global.u32 %0, [%1];"
                     : "=r"(v) : "l"(cnt) : "memory");
        if (v < GROUP_CTAS) __nanosleep(64);
    } while (v < GROUP_CTAS);
}

// Load one 128x64 fp16 tile into SMEM (conflict-free STS.128), 512 threads.
__device__ __forceinline__ void load_half(uint32_t dst, const float* __restrict__ P,
                                          float scale, int tid) {
    const int lane = tid & 31;
#pragma unroll
    for (int it = 0; it < 2; it++) {
        const int slot = (tid >> 5) * 2 + it;
        const int rg = slot >> 3, kb = slot & 7;
        const int r = rg * 32 + lane;
        const int c0 = kb * 8;
        float v[8];
#pragma unroll
        for (int j = 0; j < 8; j++) v[j] = P[(size_t)(c0 + j) * HW + r] * scale;
        uint32_t w[4];
#pragma unroll
        for (int j = 0; j < 4; j++) w[j] = pack2h(v[2 * j], v[2 * j + 1]);
        sts128(dst + swz((uint32_t)(r * 128 + kb * 16)), w[0], w[1], w[2], w[3]);
    }
}

// MMA for one tile: 4x4 warp grid, warp tile 32(m)x32(n).
__device__ __forceinline__ void mma_tile(uint32_t sb, float acc[2][4][4],
                                         int wm, int wn, int lane) {
    const int a_row = wm * 32 + (lane & 7) + ((lane >> 3) & 1) * 8;
    const int a_kb  = (lane >> 4) * 16;
    const int b_row = wn * 32 + (lane & 7) + (lane >> 4) * 8;
    const int b_kb  = ((lane >> 3) & 1) * 16;
#pragma unroll
    for (int ks = 0; ks < 4; ks++) {
        const int kbase = ks * 32;
        uint32_t ah[2][4], bf[8];
        ldsm4(sb + TILE_A + swz((uint32_t)(a_row * 128 + kbase + a_kb)), ah[0]);
        ldsm4(sb + TILE_A + swz((uint32_t)((a_row + 16) * 128 + kbase + a_kb)), ah[1]);
        ldsm4(sb + TILE_B + swz((uint32_t)(b_row * 128 + kbase + b_kb)), &bf[0]);
        ldsm4(sb + TILE_B + swz((uint32_t)((b_row + 16) * 128 + kbase + b_kb)), &bf[4]);
#pragma unroll
        for (int mi = 0; mi < 2; mi++)
#pragma unroll
            for (int ni = 0; ni < 4; ni++)
                mma16816(acc[mi][ni], ah[mi], &bf[ni * 2]);
    }
}

// exp in place + column partial sums into red; optionally park fp16x2 E.
// E word (ni,q) = half2(acc[0][ni][q], acc[1][ni][q]); v4 per ni at
// addr = E_OFF + (ni*512 + tid)*16  (512B/warp contiguous, conflict-free).
__device__ __forceinline__ void exp_sums(uint32_t sb, float acc[2][4][4], float* red,
                                         int tid, int lane, int wn, bool write_e) {
    float cs[8];
#pragma unroll
    for (int q = 0; q < 8; q++) cs[q] = 0.0f;
#pragma unroll
    for (int mi = 0; mi < 2; mi++)
#pragma unroll
        for (int ni = 0; ni < 4; ni++) {
#pragma unroll
            for (int q = 0; q < 4; q++)
                acc[mi][ni][q] = __expf(acc[mi][ni][q]);
            cs[2 * ni]     += acc[mi][ni][0] + acc[mi][ni][2];
            cs[2 * ni + 1] += acc[mi][ni][1] + acc[mi][ni][3];
        }
    if (write_e) {
#pragma unroll
        for (int ni = 0; ni < 4; ni++) {
            uint32_t w[4];
#pragma unroll
            for (int q = 0; q < 4; q++)
                w[q] = pack2h(acc[0][ni][q], acc[1][ni][q]);
            sts128(sb + E_OFF + (uint32_t)((ni * 512 + tid) * 16),
                   w[0], w[1], w[2], w[3]);
        }
    }
#pragma unroll
    for (int msk = 4; msk < 32; msk <<= 1)
#pragma unroll
        for (int q = 0; q < 8; q++)
            cs[q] += __shfl_xor_sync(0xFFFFFFFFu, cs[q], msk);
    if (lane < 4) {
#pragma unroll
        for (int ni = 0; ni < 4; ni++) {
            atomicAdd(&red[wn * 32 + ni * 8 + 2 * lane],     cs[2 * ni]);
            atomicAdd(&red[wn * 32 + ni * 8 + 2 * lane + 1], cs[2 * ni + 1]);
        }
    }
}

// Two consecutive tickets per CTA (same group 15/16: B reuse), deferred
// stores hide the group wait behind tile2's compute; tile1 parked as fp16 E.
__global__ __launch_bounds__(512, 2)
void gemm_softmax_fused(const float* __restrict__ Mk, const float* __restrict__ Qk,
                        float* __restrict__ out) {
    extern __shared__ char smem[];
    const uint32_t sb = smem_u32(smem);
    const int tid = threadIdx.x, lane = tid & 31, wid = tid >> 5;
    const int wm = wid >> 2, wn = wid & 3;

    if (tid == 0)
        *(unsigned*)(smem + TKT_OFF) = atomicAdd(&g_ticket, 2u);
    if (tid < 256) ((float*)(smem + RED1_OFF))[tid] = 0.0f;   // RED1+RED2
    __syncthreads();
    const unsigned t1 = *(const unsigned*)(smem + TKT_OFF);
    const unsigned t2 = t1 + 1;
    const int m1 = (int)(t1 & 31u), g1 = (int)(t1 >> 5);
    const int m2 = (int)(t2 & 31u), g2 = (int)(t2 >> 5);
    const int n1 = g1 & 31, b1 = g1 >> 5;
    const int n2 = g2 & 31, b2 = g2 >> 5;

    const float* A1 = Mk + (size_t)b1 * CKDIM * HW + m1 * 128;
    const float* B1 = Qk + (size_t)b1 * CKDIM * HW + n1 * 128;
    const float* A2 = Mk + (size_t)b2 * CKDIM * HW + m2 * 128;
    const float* B2 = Qk + (size_t)b2 * CKDIM * HW + n2 * 128;
    float* gs1 = &g_sums[b1 * HW + n1 * 128];
    float* gs2 = &g_sums[b2 * HW + n2 * 128];
    float* red1 = (float*)(smem + RED1_OFF);
    float* red2 = (float*)(smem + RED2_OFF);

    float acc[2][4][4];
#pragma unroll
    for (int i = 0; i < 2; i++)
#pragma unroll
        for (int j = 0; j < 4; j++)
#pragma unroll
            for (int q = 0; q < 4; q++) acc[i][j][q] = 0.0f;

    // ---- tile 1: load, MMA, exp -> fp16 E, contribute, signal ----
    load_half(sb + TILE_A, A1, 1.0f, tid);
    load_half(sb + TILE_B, B1, 0.125f, tid);
    __syncthreads();
    mma_tile(sb, acc, wm, wn, lane);
    exp_sums(sb, acc, red1, tid, lane, wn, true);
    __syncthreads();                       // red1 + E done; tile reads done
    if (tid < 128) atomicAdd(&gs1[tid], red1[tid]);

    // ---- tile 2 loads (reuse B if same group) ----
    load_half(sb + TILE_A, A2, 1.0f, tid);
    if (g2 != g1) load_half(sb + TILE_B, B2, 0.125f, tid);
    __syncthreads();                       // gs1 contributions + loads visible
    if (tid == 0) signal_grp(&g_cnt[g1]);

    // ---- tile 2: MMA, exp (stays in regs), contribute, signal ----
#pragma unroll
    for (int i = 0; i < 2; i++)
#pragma unroll
        for (int j = 0; j < 4; j++)
#pragma unroll
            for (int q = 0; q < 4; q++) acc[i][j][q] = 0.0f;
    mma_tile(sb, acc, wm, wn, lane);
    exp_sums(sb, acc, red2, tid, lane, wn, false);
    __syncthreads();
    if (tid < 128) atomicAdd(&gs2[tid], red2[tid]);
    __syncthreads();
    if (tid == 0) signal_grp(&g_cnt[g2]);

    // ---- store tile 1 from fp16 E (group long since complete) ----
    const int mrow_l = wm * 32 + (lane >> 2);
    const int ncl    = wn * 32 + 2 * (lane & 3);
    if (tid == 0) wait_grp(&g_cnt[g1]);
    __syncthreads();
    {
        float rs[8];
#pragma unroll
        for (int ni = 0; ni < 4; ni++) {
            rs[2 * ni]     = __fdividef(1.0f, __ldcg(&gs1[ncl + ni * 8]));
            rs[2 * ni + 1] = __fdividef(1.0f, __ldcg(&gs1[ncl + ni * 8 + 1]));
        }
        float* outb = out + (size_t)(b1 * HW + m1 * 128) * HW + n1 * 128;
#pragma unroll
        for (int ni = 0; ni < 4; ni++) {
            uint32_t w[4];
            lds128(sb + E_OFF + (uint32_t)((ni * 512 + tid) * 16), w);
            float e0[4], e1[4];
#pragma unroll
            for (int q = 0; q < 4; q++) {
                float2 p = __half22float2(*(__half2*)&w[q]);
                e0[q] = p.x;   // mi = 0
                e1[q] = p.y;   // mi = 1
            }
            size_t ro = (size_t)mrow_l * HW + ncl + ni * 8;
            __stcs((float2*)(outb + ro),
                   make_float2(e0[0] * rs[2 * ni], e0[1] * rs[2 * ni + 1]));
            __stcs((float2*)(outb + ro + (size_t)8 * HW),
                   make_float2(e0[2] * rs[2 * ni], e0[3] * rs[2 * ni + 1]));
            ro += (size_t)16 * HW;
            __stcs((float2*)(outb + ro),
                   make_float2(e1[0] * rs[2 * ni], e1[1] * rs[2 * ni + 1]));
            __stcs((float2*)(outb + ro + (size_t)8 * HW),
                   make_float2(e1[2] * rs[2 * ni], e1[3] * rs[2 * ni + 1]));
        }
    }

    // ---- store tile 2 from registers ----
    if (tid == 0) wait_grp(&g_cnt[g2]);
    __syncthreads();
    {
        float rs[8];
#pragma unroll
        for (int ni = 0; ni < 4; ni++) {
            rs[2 * ni]     = __fdividef(1.0f, __ldcg(&gs2[ncl + ni * 8]));
            rs[2 * ni + 1] = __fdividef(1.0f, __ldcg(&gs2[ncl + ni * 8 + 1]));
        }
        float* outb = out + (size_t)(b2 * HW + m2 * 128) * HW + n2 * 128;
#pragma unroll
        for (int mi = 0; mi < 2; mi++)
#pragma unroll
            for (int ni = 0; ni < 4; ni++) {
                size_t ro = (size_t)(mrow_l + mi * 16) * HW + ncl + ni * 8;
                __stcs((float2*)(outb + ro),
                       make_float2(acc[mi][ni][0] * rs[2 * ni],
                                   acc[mi][ni][1] * rs[2 * ni + 1]));
                __stcs((float2*)(outb + ro + (size_t)8 * HW),
                       make_float2(acc[mi][ni][2] * rs[2 * ni],
                                   acc[mi][ni][3] * rs[2 * ni + 1]));
            }
    }
}

extern "C" void kernel_launch(void* const* d_in, const int* in_sizes, int n_in,
                              void* d_out, int out_size) {
    const float* Mk = (const float*)d_in[0];
    const float* Qk = (const float*)d_in[1];
    float* out = (float*)d_out;

    cudaFuncSetAttribute(gemm_softmax_fused,
                         cudaFuncAttributeMaxDynamicSharedMemorySize, SMEM_BYTES);

    init_kernel<<<(BATCH * HW + 255) / 256, 256>>>();

    gemm_softmax_fused<<<NTILES / 2, 512, SMEM_BYTES>>>(Mk, Qk, out);
}

// round 12
// speedup vs baseline: 1.5034x; 1.1530x over previous
#include <cuda_runtime.h>
#include <cuda_fp16.h>
#include <stdint.h>

// Problem constants: B=8, CK=64, H=W=64 -> HW=4096
#define BATCH 8
#define CKDIM 64
#define HW    4096
#define NGROUPS 256           // (b, n_tile) groups: 8 * 32
#define GROUP_SIG 16          // pair-CTAs per group (32 m-tiles = 16 pairs)
#define NCTAS 2048            // each CTA: pairs c and c+2048 (2 groups, 4 tiles)

// log2(e) folded into B scale so exp(a) == exp2(d)
#define BSCALE (0.125f * 1.4426950408889634f)

// SMEM layout
#define TILE_A1 0             // pair A tile (m even): 128x64 fp16 SW128, 16 KB
#define TILE_A2 16384         // pair A tile (m odd)
#define TILE_B  32768         // Qk*BSCALE
#define E0_OFF  49152         // pair1 tile0 exp fp16: 32 KB
#define E1_OFF  81920         // pair1 tile1 exp fp16: 32 KB
#define RED_OFF 114688        // 4 x 128 floats (non-atomic)
#define TKT_OFF 116736
#define SMEM_BYTES 116752

__device__ float g_sums[BATCH * HW];
__device__ unsigned g_cnt[NGROUPS];
__device__ unsigned g_ticket;

__global__ void init_kernel() {
    int i = blockIdx.x * blockDim.x + threadIdx.x;
    if (i < BATCH * HW) g_sums[i] = 0.0f;
    if (i < NGROUPS) g_cnt[i] = 0u;
    if (i == 0) g_ticket = 0u;
}

__device__ __forceinline__ uint32_t smem_u32(const void* p) {
    uint32_t a;
    asm("{ .reg .u64 t; cvta.to.shared.u64 t, %1; cvt.u32.u64 %0, t; }"
        : "=r"(a) : "l"(p));
    return a;
}
__device__ __forceinline__ uint32_t swz(uint32_t off) {
    return off ^ ((off >> 3) & 0x70);
}
__device__ __forceinline__ uint32_t pack2h(float v0, float v1) {
    __half2 h = __floats2half2_rn(v0, v1);
    return *(uint32_t*)&h;
}
__device__ __forceinline__ float ex2(float x) {
    float r;
    asm("ex2.approx.f32 %0, %1;" : "=f"(r) : "f"(x));
    return r;
}
__device__ __forceinline__ void sts128(uint32_t addr, uint32_t r0, uint32_t r1,
                                       uint32_t r2, uint32_t r3) {
    asm volatile("st.shared.v4.b32 [%0], {%1,%2,%3,%4};"
                 :: "r"(addr), "r"(r0), "r"(r1), "r"(r2), "r"(r3));
}
__device__ __forceinline__ void lds128(uint32_t addr, uint32_t* r) {
    asm volatile("ld.shared.v4.b32 {%0,%1,%2,%3}, [%4];"
                 : "=r"(r[0]), "=r"(r[1]), "=r"(r[2]), "=r"(r[3]) : "r"(addr));
}
__device__ __forceinline__ void ldsm4(uint32_t addr, uint32_t* r) {
    asm volatile("ldmatrix.sync.aligned.m8n8.x4.shared.b16 {%0,%1,%2,%3}, [%4];"
                 : "=r"(r[0]), "=r"(r[1]), "=r"(r[2]), "=r"(r[3]) : "r"(addr));
}
__device__ __forceinline__ void mma16816(float* d, const uint32_t* a, const uint32_t* b) {
    asm volatile(
        "mma.sync.aligned.m16n8k16.row.col.f32.f16.f16.f32 "
        "{%0,%1,%2,%3}, {%4,%5,%6,%7}, {%8,%9}, {%0,%1,%2,%3};"
        : "+f"(d[0]), "+f"(d[1]), "+f"(d[2]), "+f"(d[3])
        : "r"(a[0]), "r"(a[1]), "r"(a[2]), "r"(a[3]), "r"(b[0]), "r"(b[1]));
}
__device__ __forceinline__ void signal_grp(unsigned* cnt) {
    asm volatile("red.release.gpu.global.add.u32 [%0], %1;"
                 :: "l"(cnt), "r"(1u) : "memory");
}
__device__ __forceinline__ void wait_grp(unsigned* cnt) {
    unsigned v;
    do {
        asm volatile("ld.acquire.gpu.global.u32 %0, [%1];"
                     : "=r"(v) : "l"(cnt) : "memory");
        if (v < GROUP_SIG) __nanosleep(64);
    } while (v < GROUP_SIG);
}

// Load one 128x64 fp16 tile (conflict-free STS.128), 512 threads.
__device__ __forceinline__ void load_half(uint32_t dst, const float* __restrict__ P,
                                          float scale, int tid) {
    const int lane = tid & 31;
#pragma unroll
    for (int it = 0; it < 2; it++) {
        const int slot = (tid >> 5) * 2 + it;
        const int rg = slot >> 3, kb = slot & 7;
        const int r = rg * 32 + lane;
        const int c0 = kb * 8;
        float v[8];
#pragma unroll
        for (int j = 0; j < 8; j++) v[j] = P[(size_t)(c0 + j) * HW + r] * scale;
        uint32_t w[4];
#pragma unroll
        for (int j = 0; j < 4; j++) w[j] = pack2h(v[2 * j], v[2 * j + 1]);
        sts128(dst + swz((uint32_t)(r * 128 + kb * 16)), w[0], w[1], w[2], w[3]);
    }
}

// Interleaved pair mainloop: B fragments loaded once per ks, feed both A tiles.
__device__ __forceinline__ void mma_pair(uint32_t sb, float a1[2][4][4],
                                         float a2[2][4][4], int wm, int wn, int lane) {
    const int a_row = wm * 32 + (lane & 7) + ((lane >> 3) & 1) * 8;
    const int a_kb  = (lane >> 4) * 16;
    const int b_row = wn * 32 + (lane & 7) + (lane >> 4) * 8;
    const int b_kb  = ((lane >> 3) & 1) * 16;
#pragma unroll
    for (int ks = 0; ks < 4; ks++) {
        const int kbase = ks * 32;
        uint32_t bf[8], ah1[2][4], ah2[2][4];
        ldsm4(sb + TILE_B + swz((uint32_t)(b_row * 128 + kbase + b_kb)), &bf[0]);
        ldsm4(sb + TILE_B + swz((uint32_t)((b_row + 16) * 128 + kbase + b_kb)), &bf[4]);
        ldsm4(sb + TILE_A1 + swz((uint32_t)(a_row * 128 + kbase + a_kb)), ah1[0]);
        ldsm4(sb + TILE_A1 + swz((uint32_t)((a_row + 16) * 128 + kbase + a_kb)), ah1[1]);
        ldsm4(sb + TILE_A2 + swz((uint32_t)(a_row * 128 + kbase + a_kb)), ah2[0]);
        ldsm4(sb + TILE_A2 + swz((uint32_t)((a_row + 16) * 128 + kbase + a_kb)), ah2[1]);
#pragma unroll
        for (int mi = 0; mi < 2; mi++)
#pragma unroll
            for (int ni = 0; ni < 4; ni++) {
                mma16816(a1[mi][ni], ah1[mi], &bf[ni * 2]);
                mma16816(a2[mi][ni], ah2[mi], &bf[ni * 2]);
            }
    }
}

// exp2 both accs, combined column sums (same group!), optional fp16 E park,
// non-atomic RED[wm][128] write.
__device__ __forceinline__ void exp_pair(uint32_t sb, float a1[2][4][4],
                                         float a2[2][4][4], int tid, int lane,
                                         int wm, int wn, bool write_e) {
    float cs[8];
#pragma unroll
    for (int q = 0; q < 8; q++) cs[q] = 0.0f;
#pragma unroll
    for (int mi = 0; mi < 2; mi++)
#pragma unroll
        for (int ni = 0; ni < 4; ni++) {
#pragma unroll
            for (int q = 0; q < 4; q++) {
                a1[mi][ni][q] = ex2(a1[mi][ni][q]);
                a2[mi][ni][q] = ex2(a2[mi][ni][q]);
            }
            cs[2 * ni]     += a1[mi][ni][0] + a1[mi][ni][2] + a2[mi][ni][0] + a2[mi][ni][2];
            cs[2 * ni + 1] += a1[mi][ni][1] + a1[mi][ni][3] + a2[mi][ni][1] + a2[mi][ni][3];
        }
    if (write_e) {
#pragma unroll
        for (int ni = 0; ni < 4; ni++) {
            uint32_t w[4];
#pragma unroll
            for (int q = 0; q < 4; q++) w[q] = pack2h(a1[0][ni][q], a1[1][ni][q]);
            sts128(sb + E0_OFF + (uint32_t)((ni * 512 + tid) * 16), w[0], w[1], w[2], w[3]);
#pragma unroll
            for (int q = 0; q < 4; q++) w[q] = pack2h(a2[0][ni][q], a2[1][ni][q]);
            sts128(sb + E1_OFF + (uint32_t)((ni * 512 + tid) * 16), w[0], w[1], w[2], w[3]);
        }
    }
#pragma unroll
    for (int msk = 4; msk < 32; msk <<= 1)
#pragma unroll
        for (int q = 0; q < 8; q++)
            cs[q] += __shfl_xor_sync(0xFFFFFFFFu, cs[q], msk);
    if (lane < 4) {
        float* red = (float*)((char*)0 + 0); // silence unused warn pattern
        (void)red;
        float* R = (float*)0;
        (void)R;
#pragma unroll
        for (int ni = 0; ni < 4; ni++) {
            uint32_t base = (uint32_t)(RED_OFF + (wm * 128 + wn * 32 + ni * 8 + 2 * lane) * 4);
            asm volatile("st.shared.b32 [%0], %1;" :: "r"(sb + base), "f"(cs[2 * ni]));
            asm volatile("st.shared.b32 [%0], %1;" :: "r"(sb + base + 4), "f"(cs[2 * ni + 1]));
        }
    }
}

// Store one parked tile from E.
__device__ __forceinline__ void store_from_E(uint32_t sb, uint32_t eoff,
                                             const float* rs, float* __restrict__ outb,
                                             int tid, int mrow_l, int ncl) {
#pragma unroll
    for (int ni = 0; ni < 4; ni++) {
        uint32_t w[4];
        lds128(sb + eoff + (uint32_t)((ni * 512 + tid) * 16), w);
        float e0[4], e1[4];
#pragma unroll
        for (int q = 0; q < 4; q++) {
            float2 p = __half22float2(*(__half2*)&w[q]);
            e0[q] = p.x; e1[q] = p.y;
        }
        size_t ro = (size_t)mrow_l * HW + ncl + ni * 8;
        __stcs((float2*)(outb + ro),
               make_float2(e0[0] * rs[2 * ni], e0[1] * rs[2 * ni + 1]));
        __stcs((float2*)(outb + ro + (size_t)8 * HW),
               make_float2(e0[2] * rs[2 * ni], e0[3] * rs[2 * ni + 1]));
        ro += (size_t)16 * HW;
        __stcs((float2*)(outb + ro),
               make_float2(e1[0] * rs[2 * ni], e1[1] * rs[2 * ni + 1]));
        __stcs((float2*)(outb + ro + (size_t)8 * HW),
               make_float2(e1[2] * rs[2 * ni], e1[3] * rs[2 * ni + 1]));
    }
}

// Store one tile from registers.
__device__ __forceinline__ void store_from_regs(const float acc[2][4][4],
                                                const float* rs, float* __restrict__ outb,
                                                int mrow_l, int ncl) {
#pragma unroll
    for (int mi = 0; mi < 2; mi++)
#pragma unroll
        for (int ni = 0; ni < 4; ni++) {
            size_t ro = (size_t)(mrow_l + mi * 16) * HW + ncl + ni * 8;
            __stcs((float2*)(outb + ro),
                   make_float2(acc[mi][ni][0] * rs[2 * ni], acc[mi][ni][1] * rs[2 * ni + 1]));
            __stcs((float2*)(outb + ro + (size_t)8 * HW),
                   make_float2(acc[mi][ni][2] * rs[2 * ni], acc[mi][ni][3] * rs[2 * ni + 1]));
        }
}

// 4 tiles per CTA: pair1 (group g1) -> E, pair2 (group g2) -> regs.
// Waits hidden behind pair2 compute / pair1 stores.
__global__ __launch_bounds__(512, 1)
void gemm_softmax_fused(const float* __restrict__ Mk, const float* __restrict__ Qk,
                        float* __restrict__ out) {
    extern __shared__ char smem[];
    const uint32_t sb = smem_u32(smem);
    const int tid = threadIdx.x, lane = tid & 31, wid = tid >> 5;
    const int wm = wid >> 2, wn = wid & 3;
    float* RED = (float*)(smem + RED_OFF);

    if (tid == 0)
        *(unsigned*)(smem + TKT_OFF) = atomicAdd(&g_ticket, 1u);
    __syncthreads();
    const unsigned c = *(const unsigned*)(smem + TKT_OFF);

    const unsigned p1 = c, p2 = c + NCTAS;
    const int g1 = (int)(p1 >> 4), mp1 = (int)(p1 & 15u);
    const int g2 = (int)(p2 >> 4), mp2 = (int)(p2 & 15u);
    const int n1 = (g1 & 31) * 128, b1 = g1 >> 5;
    const int n2 = (g2 & 31) * 128, b2 = g2 >> 5;

    const float* A1p = Mk + (size_t)b1 * CKDIM * HW + mp1 * 256;
    const float* B1p = Qk + (size_t)b1 * CKDIM * HW + n1;
    const float* A2p = Mk + (size_t)b2 * CKDIM * HW + mp2 * 256;
    const float* B2p = Qk + (size_t)b2 * CKDIM * HW + n2;
    float* gs1 = &g_sums[b1 * HW + n1];
    float* gs2 = &g_sums[b2 * HW + n2];

    float acc1[2][4][4], acc2[2][4][4];
#pragma unroll
    for (int i = 0; i < 2; i++)
#pragma unroll
        for (int j = 0; j < 4; j++)
#pragma unroll
            for (int q = 0; q < 4; q++) { acc1[i][j][q] = 0.f; acc2[i][j][q] = 0.f; }

    // ---- pair 1: load (2 A tiles + B), interleaved MMA, exp -> E, reduce ----
    load_half(sb + TILE_A1, A1p, 1.0f, tid);
    load_half(sb + TILE_A2, A1p + 128, 1.0f, tid);
    load_half(sb + TILE_B, B1p, BSCALE, tid);
    __syncthreads();
    mma_pair(sb, acc1, acc2, wm, wn, lane);
    exp_pair(sb, acc1, acc2, tid, lane, wm, wn, true);
    __syncthreads();                       // E + RED done; tile bufs free
    if (tid < 128)
        atomicAdd(&gs1[tid], RED[tid] + RED[128 + tid] + RED[256 + tid] + RED[384 + tid]);

    // ---- pair 2 loads (overlap with gs1 atomic latency) ----
    load_half(sb + TILE_A1, A2p, 1.0f, tid);
    load_half(sb + TILE_A2, A2p + 128, 1.0f, tid);
    load_half(sb + TILE_B, B2p, BSCALE, tid);
    __syncthreads();                       // gs1 contributions + loads visible
    if (tid == 0) signal_grp(&g_cnt[g1]);

    // ---- pair 2: interleaved MMA, exp (stays in regs), reduce, signal ----
#pragma unroll
    for (int i = 0; i < 2; i++)
#pragma unroll
        for (int j = 0; j < 4; j++)
#pragma unroll
            for (int q = 0; q < 4; q++) { acc1[i][j][q] = 0.f; acc2[i][j][q] = 0.f; }
    mma_pair(sb, acc1, acc2, wm, wn, lane);
    exp_pair(sb, acc1, acc2, tid, lane, wm, wn, false);
    __syncthreads();
    if (tid < 128)
        atomicAdd(&gs2[tid], RED[tid] + RED[128 + tid] + RED[256 + tid] + RED[384 + tid]);
    __syncthreads();
    if (tid == 0) signal_grp(&g_cnt[g2]);

    const int mrow_l = wm * 32 + (lane >> 2);
    const int ncl    = wn * 32 + 2 * (lane & 3);

    // ---- store pair 1 from E (wait long since satisfied) ----
    if (tid == 0) wait_grp(&g_cnt[g1]);
    __syncthreads();
    {
        float rs[8];
#pragma unroll
        for (int ni = 0; ni < 4; ni++) {
            rs[2 * ni]     = __fdividef(1.0f, __ldcg(&gs1[ncl + ni * 8]));
            rs[2 * ni + 1] = __fdividef(1.0f, __ldcg(&gs1[ncl + ni * 8 + 1]));
        }
        float* outb = out + (size_t)(b1 * HW + mp1 * 256) * HW + n1;
        store_from_E(sb, E0_OFF, rs, outb, tid, mrow_l, ncl);
        store_from_E(sb, E1_OFF, rs, outb + (size_t)128 * HW, tid, mrow_l, ncl);
    }

    // ---- store pair 2 from registers ----
    if (tid == 0) wait_grp(&g_cnt[g2]);
    __syncthreads();
    {
        float rs[8];
#pragma unroll
        for (int ni = 0; ni < 4; ni++) {
            rs[2 * ni]     = __fdividef(1.0f, __ldcg(&gs2[ncl + ni * 8]));
            rs[2 * ni + 1] = __fdividef(1.0f, __ldcg(&gs2[ncl + ni * 8 + 1]));
        }
        float* outb = out + (size_t)(b2 * HW + mp2 * 256) * HW + n2;
        store_from_regs(acc1, rs, outb, mrow_l, ncl);
        store_from_regs(acc2, rs, outb + (size_t)128 * HW, mrow_l, ncl);
    }
}

extern "C" void kernel_launch(void* const* d_in, const int* in_sizes, int n_in,
                              void* d_out, int out_size) {
    const float* Mk = (const float*)d_in[0];
    const float* Qk = (const float*)d_in[1];
    float* out = (float*)d_out;

    cudaFuncSetAttribute(gemm_softmax_fused,
                         cudaFuncAttributeMaxDynamicSharedMemorySize, SMEM_BYTES);

    init_kernel<<<(BATCH * HW + 255) / 256, 256>>>();

    gemm_softmax_fused<<<NCTAS, 512, SMEM_BYTES>>>(Mk, Qk, out);
}